// round 4
// baseline (speedup 1.0000x reference)
#include <cuda_runtime.h>
#include <cuda_bf16.h>

// IoUMetricLoss: pred_label fp32 [8,19,512,1024], label int32 [8,512,1024]
// out: scalar fp32 = 1 - nanmean(IoU per class), all-NaN -> 0.5
//
// R4: 8 pixels (2x float4) per thread -> 2 independent load streams per
// class iteration, doubling MLP to hide DRAM latency (R3 showed DRAM=72.8%,
// issue=22% -> long-scoreboard bound at MLP~6). Grid 2048 blocks; fused
// last-block finalize with self-resetting accumulators.

#define NUM_CLASSES 19
#define HW_SHIFT 19                  // 512*1024 = 2^19
#define HW (1 << HW_SHIFT)
#define BATCH 8
#define TOTAL_PIX (BATCH * HW)       // 4194304
#define PIX_PER_THREAD 8
#define HIST_BLOCK 256
#define WARPS_PER_BLOCK (HIST_BLOCK / 32)
#define GRID_BLOCKS (TOTAL_PIX / PIX_PER_THREAD / HIST_BLOCK)  // 2048

// Global accumulators (no cudaMalloc allowed). Statically zero; the
// finalizing block re-zeros them so every graph replay sees clean state.
// g_li[c]: low 32 = area_label, high 32 = area_intersect.
__device__ unsigned long long g_li[NUM_CLASSES];
__device__ unsigned int       g_pred[NUM_CLASSES];
__device__ unsigned int       g_done;

__device__ __forceinline__ void amax_step(float v, float& bv, int& bi, int c) {
    // value chain: 4-cyc FMNMX; index select off the critical path
    float m = fmaxf(bv, v);
    bi = (v > bv) ? c : bi;
    bv = m;
}

__global__ void __launch_bounds__(HIST_BLOCK, 4)
iou_fused_kernel(const float* __restrict__ pred,
                 const int* __restrict__ label,
                 float* __restrict__ out) {
    __shared__ unsigned long long s_li[WARPS_PER_BLOCK][NUM_CLASSES];
    __shared__ unsigned int       s_pr[WARPS_PER_BLOCK][NUM_CLASSES];
    __shared__ int                s_is_last;

    const int warp = threadIdx.x >> 5;
    const int lane = threadIdx.x & 31;

    if (lane < NUM_CLASSES) {
        s_li[warp][lane] = 0ULL;
        s_pr[warp][lane] = 0u;
    }
    __syncwarp();

    const unsigned t  = blockIdx.x * blockDim.x + threadIdx.x;  // 0..524287
    const unsigned P  = t * PIX_PER_THREAD;     // first of 8 consecutive pixels
    const unsigned b  = P >> HW_SHIFT;          // batch (8 pixels never split)
    const unsigned hw = P & (HW - 1);

    const float* base = pred + ((size_t)b * NUM_CLASSES << HW_SHIFT) + hw;

    // two independent float4 streams per class -> 2x MLP
    float4 av = __ldcs((const float4*)base);
    float4 bv = __ldcs((const float4*)(base + 4));
    int ai0 = 0, ai1 = 0, ai2 = 0, ai3 = 0;
    int bi0 = 0, bi1 = 0, bi2 = 0, bi3 = 0;

    #pragma unroll
    for (int c = 1; c < NUM_CLASSES; c++) {
        const float* p = base + ((size_t)c << HW_SHIFT);
        float4 va = __ldcs((const float4*)p);
        float4 vb = __ldcs((const float4*)(p + 4));
        amax_step(va.x, av.x, ai0, c);
        amax_step(va.y, av.y, ai1, c);
        amax_step(va.z, av.z, ai2, c);
        amax_step(va.w, av.w, ai3, c);
        amax_step(vb.x, bv.x, bi0, c);
        amax_step(vb.y, bv.y, bi1, c);
        amax_step(vb.z, bv.z, bi2, c);
        amax_step(vb.w, bv.w, bi3, c);
    }

    // labels: 8 consecutive int32 = two 16B loads
    int4 la = __ldcs((const int4*)(label + P));
    int4 lb = __ldcs((const int4*)(label + P + 4));

    #define ACC(l, i)                                                          \
        if ((l) >= 0) {                                                        \
            atomicAdd(&s_li[warp][(l)],                                        \
                      1ULL | (((i) == (l)) ? (1ULL << 32) : 0ULL));            \
            atomicAdd(&s_pr[warp][(i)], 1u);                                   \
        }
    ACC(la.x, ai0); ACC(la.y, ai1); ACC(la.z, ai2); ACC(la.w, ai3);
    ACC(lb.x, bi0); ACC(lb.y, bi1); ACC(lb.z, bi2); ACC(lb.w, bi3);
    #undef ACC

    __syncthreads();

    // block reduce: one global atomic per class per counter
    if (threadIdx.x < NUM_CLASSES) {
        unsigned long long li = 0ULL;
        unsigned int       pr = 0u;
        #pragma unroll
        for (int w = 0; w < WARPS_PER_BLOCK; w++) {
            li += s_li[w][threadIdx.x];
            pr += s_pr[w][threadIdx.x];
        }
        atomicAdd(&g_li[threadIdx.x], li);
        atomicAdd(&g_pred[threadIdx.x], pr);
    }
    __syncthreads();

    // last-block-done finalize + state reset
    if (threadIdx.x == 0) {
        __threadfence();
        unsigned prev = atomicAdd(&g_done, 1u);
        s_is_last = (prev == gridDim.x - 1);
    }
    __syncthreads();
    if (!s_is_last) return;

    if (threadIdx.x < 32) {
        const int c = threadIdx.x;
        float iou_sum = 0.0f;
        int   valid   = 0;
        if (c < NUM_CLASSES) {
            unsigned long long li = g_li[c];
            unsigned int pr    = g_pred[c];
            unsigned int lab   = (unsigned int)(li & 0xFFFFFFFFULL);
            unsigned int inter = (unsigned int)(li >> 32);
            unsigned long long uni =
                (unsigned long long)lab + (unsigned long long)pr
                - (unsigned long long)inter;
            if (uni > 0ULL) {
                iou_sum = (float)inter / (float)uni;
                valid   = 1;
            }
            // uni == 0 -> 0/0 = NaN in reference, excluded by nanmean
            g_li[c]   = 0ULL;   // reset for next graph replay
            g_pred[c] = 0u;
        }
        #pragma unroll
        for (int o = 16; o > 0; o >>= 1) {
            iou_sum += __shfl_down_sync(0xFFFFFFFFu, iou_sum, o);
            valid   += __shfl_down_sync(0xFFFFFFFFu, valid, o);
        }
        if (c == 0) {
            g_done = 0u;
            float loss = (valid > 0) ? (1.0f - iou_sum / (float)valid) : 0.5f;
            *out = loss;
        }
    }
}

extern "C" void kernel_launch(void* const* d_in, const int* in_sizes, int n_in,
                              void* d_out, int out_size) {
    // pred = 79,691,776 elems; label = 4,194,304 (resolve by size).
    const float* pred;
    const int*   label;
    if (in_sizes[0] >= in_sizes[1]) {
        pred  = (const float*)d_in[0];
        label = (const int*)d_in[1];
    } else {
        pred  = (const float*)d_in[1];
        label = (const int*)d_in[0];
    }
    float* out = (float*)d_out;

    iou_fused_kernel<<<GRID_BLOCKS, HIST_BLOCK>>>(pred, label, out);
}

// round 5
// speedup vs baseline: 1.1555x; 1.1555x over previous
#include <cuda_runtime.h>
#include <cuda_bf16.h>

// IoUMetricLoss: pred_label fp32 [8,19,512,1024], label int32 [8,512,1024]
// out: scalar fp32 = 1 - nanmean(IoU per class), all-NaN -> 0.5
//
// R5: back to R3 grid shape (4 px/thread, 4096x256 blocks — good wave
// balance), but the 19 class loads are issued in two explicit register
// batches (12 + 7) so ~12 loads/warp are in flight -> ~12 KB outstanding
// per SM, matching the BW*latency product. R3 measured DRAM=72.8% at
// MLP~6; this targets 83-88%.

#define NUM_CLASSES 19
#define HW_SHIFT 19                  // 512*1024 = 2^19
#define HW (1 << HW_SHIFT)
#define BATCH 8
#define TOTAL_PIX (BATCH * HW)       // 4194304
#define VEC_GROUPS (TOTAL_PIX / 4)   // 1048576
#define HIST_BLOCK 256
#define WARPS_PER_BLOCK (HIST_BLOCK / 32)
#define GRID_BLOCKS (VEC_GROUPS / HIST_BLOCK)   // 4096
#define BATCH1 12                    // classes 0..11 in flight together
#define BATCH2 (NUM_CLASSES - BATCH1)

// Global accumulators (no cudaMalloc allowed). Statically zero; the
// finalizing block re-zeros them so every graph replay sees clean state.
// g_li[c]: low 32 = area_label, high 32 = area_intersect.
__device__ unsigned long long g_li[NUM_CLASSES];
__device__ unsigned int       g_pred[NUM_CLASSES];
__device__ unsigned int       g_done;

__device__ __forceinline__ void amax_step(float v, float& bv, int& bi, int c) {
    float m = fmaxf(bv, v);
    bi = (v > bv) ? c : bi;
    bv = m;
}

__global__ void __launch_bounds__(HIST_BLOCK)
iou_fused_kernel(const float* __restrict__ pred,
                 const int* __restrict__ label,
                 float* __restrict__ out) {
    __shared__ unsigned long long s_li[WARPS_PER_BLOCK][NUM_CLASSES];
    __shared__ unsigned int       s_pr[WARPS_PER_BLOCK][NUM_CLASSES];
    __shared__ int                s_is_last;

    const int warp = threadIdx.x >> 5;
    const int lane = threadIdx.x & 31;

    if (lane < NUM_CLASSES) {
        s_li[warp][lane] = 0ULL;
        s_pr[warp][lane] = 0u;
    }
    __syncwarp();

    const unsigned t  = blockIdx.x * blockDim.x + threadIdx.x;  // 0..VEC_GROUPS-1
    const unsigned P  = t << 2;                 // first of 4 consecutive pixels
    const unsigned b  = P >> HW_SHIFT;          // batch index
    const unsigned hw = P & (HW - 1);

    const float* base = pred + ((size_t)b * NUM_CLASSES << HW_SHIFT) + hw;

    // label first — independent stream, issued before the class batches
    int4 lv = __ldcs((const int4*)(label + P));

    // ---- batch 1: classes 0..11, twelve independent 16B loads in flight ----
    float4 v[BATCH1];
    #pragma unroll
    for (int c = 0; c < BATCH1; c++)
        v[c] = __ldcs((const float4*)(base + ((size_t)c << HW_SHIFT)));

    float4 bv = v[0];
    int i0 = 0, i1 = 0, i2 = 0, i3 = 0;
    #pragma unroll
    for (int c = 1; c < BATCH1; c++) {
        amax_step(v[c].x, bv.x, i0, c);
        amax_step(v[c].y, bv.y, i1, c);
        amax_step(v[c].z, bv.z, i2, c);
        amax_step(v[c].w, bv.w, i3, c);
    }

    // ---- batch 2: classes 12..18, seven independent loads in flight ----
    float4 w[BATCH2];
    #pragma unroll
    for (int c = 0; c < BATCH2; c++)
        w[c] = __ldcs((const float4*)(base + ((size_t)(c + BATCH1) << HW_SHIFT)));

    #pragma unroll
    for (int c = 0; c < BATCH2; c++) {
        amax_step(w[c].x, bv.x, i0, c + BATCH1);
        amax_step(w[c].y, bv.y, i1, c + BATCH1);
        amax_step(w[c].z, bv.z, i2, c + BATCH1);
        amax_step(w[c].w, bv.w, i3, c + BATCH1);
    }

    // accumulate: packed label(+intersect) atomic + pred atomic, per pixel
    #define ACC(l, i)                                                          \
        if ((l) >= 0) {                                                        \
            atomicAdd(&s_li[warp][(l)],                                        \
                      1ULL | (((i) == (l)) ? (1ULL << 32) : 0ULL));            \
            atomicAdd(&s_pr[warp][(i)], 1u);                                   \
        }
    ACC(lv.x, i0); ACC(lv.y, i1); ACC(lv.z, i2); ACC(lv.w, i3);
    #undef ACC

    __syncthreads();

    // block reduce: one global atomic per class per counter
    if (threadIdx.x < NUM_CLASSES) {
        unsigned long long li = 0ULL;
        unsigned int       pr = 0u;
        #pragma unroll
        for (int w2 = 0; w2 < WARPS_PER_BLOCK; w2++) {
            li += s_li[w2][threadIdx.x];
            pr += s_pr[w2][threadIdx.x];
        }
        atomicAdd(&g_li[threadIdx.x], li);
        atomicAdd(&g_pred[threadIdx.x], pr);
    }
    __syncthreads();

    // last-block-done finalize + state reset
    if (threadIdx.x == 0) {
        __threadfence();
        unsigned prev = atomicAdd(&g_done, 1u);
        s_is_last = (prev == gridDim.x - 1);
    }
    __syncthreads();
    if (!s_is_last) return;

    if (threadIdx.x < 32) {
        const int c = threadIdx.x;
        float iou_sum = 0.0f;
        int   valid   = 0;
        if (c < NUM_CLASSES) {
            unsigned long long li = g_li[c];
            unsigned int pr    = g_pred[c];
            unsigned int lab   = (unsigned int)(li & 0xFFFFFFFFULL);
            unsigned int inter = (unsigned int)(li >> 32);
            unsigned long long uni =
                (unsigned long long)lab + (unsigned long long)pr
                - (unsigned long long)inter;
            if (uni > 0ULL) {
                iou_sum = (float)inter / (float)uni;
                valid   = 1;
            }
            // uni == 0 -> 0/0 = NaN in reference, excluded by nanmean
            g_li[c]   = 0ULL;   // reset for next graph replay
            g_pred[c] = 0u;
        }
        #pragma unroll
        for (int o = 16; o > 0; o >>= 1) {
            iou_sum += __shfl_down_sync(0xFFFFFFFFu, iou_sum, o);
            valid   += __shfl_down_sync(0xFFFFFFFFu, valid, o);
        }
        if (c == 0) {
            g_done = 0u;
            float loss = (valid > 0) ? (1.0f - iou_sum / (float)valid) : 0.5f;
            *out = loss;
        }
    }
}

extern "C" void kernel_launch(void* const* d_in, const int* in_sizes, int n_in,
                              void* d_out, int out_size) {
    // pred = 79,691,776 elems; label = 4,194,304 (resolve by size).
    const float* pred;
    const int*   label;
    if (in_sizes[0] >= in_sizes[1]) {
        pred  = (const float*)d_in[0];
        label = (const int*)d_in[1];
    } else {
        pred  = (const float*)d_in[1];
        label = (const int*)d_in[0];
    }
    float* out = (float*)d_out;

    iou_fused_kernel<<<GRID_BLOCKS, HIST_BLOCK>>>(pred, label, out);
}